// round 4
// baseline (speedup 1.0000x reference)
#include <cuda_runtime.h>
#include <cstdint>

#define NBMAX 2048
__device__ float g_partial[NBMAX];
__device__ unsigned g_count;

// monotone-in-atan2 sortable key: (pseudo-angle bits & ~31) | index
__device__ __forceinline__ unsigned angle_key(float cx, float cy, int i) {
    float den = fabsf(cx) + fabsf(cy);
    den = (den == 0.f) ? 1.f : den;
    float pa = copysignf(1.f - __fdividef(cx, den), cy);  // diamond angle, monotone in atan2
    int ib = __float_as_int(pa);
    unsigned u = (unsigned)(ib ^ ((ib >> 31) | 0x80000000));
    return (u & 0xFFFFFFE0u) | (unsigned)i;
}

__device__ __forceinline__ void bitonic_sort8(unsigned (&key)[8]) {
#pragma unroll
    for (int k = 2; k <= 8; k <<= 1)
#pragma unroll
        for (int j = k >> 1; j > 0; j >>= 1)
#pragma unroll
            for (int i = 0; i < 8; i++) {
                int l = i ^ j;
                if (l > i) {
                    unsigned a = key[i], b = key[l];
                    unsigned lo = min(a, b), hi = max(a, b);
                    if ((i & k) == 0) { key[i] = lo; key[l] = hi; }
                    else              { key[i] = hi; key[l] = lo; }
                }
            }
}

// One Sutherland-Hodgman pass: keep points with SGN*coord(AX) <= lim.
// MAXN = static bound on input count n. Returns output count.
template <int MAXN, bool AX, int SGN>
__device__ __forceinline__ int clip_pass(const float* qx, const float* qy, int n,
                                         float lim, float* ox, float* oy) {
    int m = 0;
#pragma unroll
    for (int i = 0; i < MAXN; i++) {
        if (i < n) {
            float cx = qx[i], cy = qy[i];
            int j = (i + 1 == n) ? 0 : i + 1;
            float nx = qx[j], ny = qy[j];
            float dc = lim - (float)SGN * (AX ? cx : cy);  // >= 0 -> inside
            float dn = lim - (float)SGN * (AX ? nx : ny);
            bool inc = dc >= 0.f;
            bool inn = dn >= 0.f;
            if (inc) { ox[m] = cx; oy[m] = cy; m++; }
            if (inc != inn) {
                float t = __fdividef(dc, dc - dn);
                ox[m] = cx + t * (nx - cx);
                oy[m] = cy + t * (ny - cy);
                m++;
            }
        }
    }
    return m;
}

__global__ void __launch_bounds__(256) poly_giou_kernel(const float* __restrict__ pred,
                                                        const float* __restrict__ target,
                                                        const float* __restrict__ weight,
                                                        float* __restrict__ out,
                                                        int N, int nblocks) {
    const float dxc[4] = {0.5f, -0.5f, -0.5f, 0.5f};
    const float dyc[4] = {0.5f, 0.5f, -0.5f, -0.5f};

    float acc = 0.f;
    int stride = gridDim.x * blockDim.x;
    for (int idx = blockIdx.x * blockDim.x + threadIdx.x; idx < N; idx += stride) {
        float p0 = pred[5 * idx + 0], p1 = pred[5 * idx + 1];
        float p2 = pred[5 * idx + 2], p3 = pred[5 * idx + 3], p4 = pred[5 * idx + 4];
        float t0 = target[5 * idx + 0], t1 = target[5 * idx + 1];
        float t2 = target[5 * idx + 2], t3 = target[5 * idx + 3], t4 = target[5 * idx + 4];

        // work entirely in the target box's frame (rigid motion preserves all areas)
        float st, ct, sd, cd;
        __sincosf(t4, &st, &ct);
        __sincosf(p4 - t4, &sd, &cd);
        float rx = p0 - t0, ry = p1 - t1;
        float dx = ct * rx + st * ry;   // R(-t4) * (p_xy - t_xy)
        float dy = -st * rx + ct * ry;

        float a = 0.5f * t2;  // target half-extents
        float b = 0.5f * t3;

        // pred corners in target frame (CCW)
        float Ax[8], Ay[8], Bx[8], By[8];
#pragma unroll
        for (int k = 0; k < 4; k++) {
            float cx = dxc[k] * p2, cy = dyc[k] * p3;
            Ax[k] = cx * cd - cy * sd + dx;
            Ay[k] = cx * sd + cy * cd + dy;
        }

        // ---- overlap: clip pred quad against axis-aligned target rect ----
        int n = 4;
        n = clip_pass<4, true, 1>(Ax, Ay, n, a, Bx, By);    // x <=  a
        n = clip_pass<5, true, -1>(Bx, By, n, a, Ax, Ay);   // x >= -a
        n = clip_pass<6, false, 1>(Ax, Ay, n, b, Bx, By);   // y <=  b
        n = clip_pass<7, false, -1>(Bx, By, n, b, Ax, Ay);  // y >= -b

        float s = 0.f;
#pragma unroll
        for (int i = 0; i < 8; i++) {
            if (i < n) {
                int j = (i + 1 == n) ? 0 : i + 1;
                s += Ax[i] * Ay[j] - Ay[i] * Ax[j];
            }
        }
        float overlap = fabsf(s) * 0.5f;

        // ---- enclose: star polygon (angular sort about centroid) of 8 corners ----
        float ex[8], ey[8];
#pragma unroll
        for (int k = 0; k < 4; k++) {
            float cx = dxc[k] * p2, cy = dyc[k] * p3;
            ex[k] = cx * cd - cy * sd + dx;
            ey[k] = cx * sd + cy * cd + dy;
            ex[4 + k] = dxc[k] * t2;
            ey[4 + k] = dyc[k] * t3;
        }
        float emx = 0.f, emy = 0.f;
#pragma unroll
        for (int i = 0; i < 8; i++) { emx += ex[i]; emy += ey[i]; }
        emx *= 0.125f; emy *= 0.125f;
        unsigned ek[8];
#pragma unroll
        for (int i = 0; i < 8; i++) ek[i] = angle_key(ex[i] - emx, ey[i] - emy, i);
        bitonic_sort8(ek);
        float es = 0.f;
#pragma unroll
        for (int i = 0; i < 8; i++) {
            int j = (i + 1) & 7;
            unsigned ci = ek[i] & 31u, cj = ek[j] & 31u;
            es += ex[ci] * ey[cj] - ey[ci] * ex[cj];
        }
        float enclose = fabsf(es) * 0.5f;

        float uni = p2 * p3 + t2 * t3 - overlap + 1e-6f;
        float iou = fmaxf(__fdividef(overlap, uni), 1e-6f);
        float giou = iou - __fdividef(enclose - uni, enclose);
        acc += (1.f - giou) * weight[idx];
    }

    // deterministic block reduction
    float v = acc;
#pragma unroll
    for (int o = 16; o > 0; o >>= 1) v += __shfl_down_sync(0xFFFFFFFFu, v, o);
    __shared__ float ws[8];
    __shared__ bool is_last;
    int lane = threadIdx.x & 31;
    int wid = threadIdx.x >> 5;
    if (lane == 0) ws[wid] = v;
    __syncthreads();
    if (wid == 0) {
        float t = (lane < 8) ? ws[lane] : 0.f;
#pragma unroll
        for (int o = 4; o > 0; o >>= 1) t += __shfl_down_sync(0xFFFFFFFFu, t, o);
        if (lane == 0) {
            g_partial[blockIdx.x] = t;
            __threadfence();
            unsigned old = atomicAdd(&g_count, 1u);
            is_last = (old == (unsigned)(nblocks - 1));
        }
    }
    __syncthreads();

    // last block performs the final deterministic reduction
    if (is_last) {
        __threadfence();
        double s = 0.0;
        for (int i = threadIdx.x; i < nblocks; i += blockDim.x) s += (double)g_partial[i];
        __shared__ double sh[256];
        sh[threadIdx.x] = s;
        __syncthreads();
#pragma unroll
        for (int o = 128; o > 0; o >>= 1) {
            if (threadIdx.x < o) sh[threadIdx.x] += sh[threadIdx.x + o];
            __syncthreads();
        }
        if (threadIdx.x == 0) {
            out[0] = (float)(sh[0] / (double)N);
            g_count = 0u;  // reset for next graph replay
        }
    }
}

extern "C" void kernel_launch(void* const* d_in, const int* in_sizes, int n_in,
                              void* d_out, int out_size) {
    const float* pred = (const float*)d_in[0];
    const float* target = (const float*)d_in[1];
    const float* weight = (const float*)d_in[2];
    int N = in_sizes[2];

    int threads = 256;
    int blocks = (N + threads - 1) / threads;
    if (blocks > NBMAX) blocks = NBMAX;

    poly_giou_kernel<<<blocks, threads>>>(pred, target, weight, (float*)d_out, N, blocks);
}

// round 5
// speedup vs baseline: 1.4554x; 1.4554x over previous
#include <cuda_runtime.h>
#include <cstdint>

#define NBMAX 2048
__device__ float g_partial[NBMAX];
__device__ unsigned g_count;

// monotone-in-atan2 sortable key: (pseudo-angle bits & ~31) | index
__device__ __forceinline__ unsigned angle_key(float cx, float cy, int i) {
    float den = fabsf(cx) + fabsf(cy);
    den = (den == 0.f) ? 1.f : den;
    float pa = copysignf(1.f - __fdividef(cx, den), cy);  // diamond angle, monotone in atan2
    int ib = __float_as_int(pa);
    unsigned u = (unsigned)(ib ^ ((ib >> 31) | 0x80000000));
    return (u & 0xFFFFFFE0u) | (unsigned)i;
}

// Clamp-clip one directed edge (c -> n) against cc in [-lim, lim].
// cc/cn = coordinate being clamped; oc/on = the other coordinate.
// Emits exactly 3 points (with duplicates when crossings are absent):
//   a0 = clamped current vertex, a1 = first crossing, a2 = second crossing.
__device__ __forceinline__ void clip_edge(float cc, float oc, float cn, float on, float lim,
                                          float& a0c, float& a0o,
                                          float& a1c, float& a1o,
                                          float& a2c, float& a2o) {
    float d = cn - cc;
    bool hl = (cc < -lim) != (cn < -lim);
    bool hh = (cc > lim) != (cn > lim);
    float inv = __fdividef(1.f, d);
    float od = on - oc;
    float o_lo = oc + ((-lim - cc) * inv) * od;
    float o_hi = oc + ((lim - cc) * inv) * od;
    a0c = fminf(fmaxf(cc, -lim), lim);
    a0o = oc;
    bool lo_first = d > 0.f;
    bool first_lo = hl && (lo_first || !hh);
    bool hasf = hl || hh;
    a1c = hasf ? (first_lo ? -lim : lim) : a0c;
    a1o = hasf ? (first_lo ? o_lo : o_hi) : a0o;
    bool both = hl && hh;
    a2c = both ? (lo_first ? lim : -lim) : a1c;
    a2o = both ? (lo_first ? o_hi : o_lo) : a1o;
}

__global__ void __launch_bounds__(256) poly_giou_kernel(const float* __restrict__ pred,
                                                        const float* __restrict__ target,
                                                        const float* __restrict__ weight,
                                                        float* __restrict__ out,
                                                        int N, int nblocks) {
    const float dxc[4] = {0.5f, -0.5f, -0.5f, 0.5f};
    const float dyc[4] = {0.5f, 0.5f, -0.5f, -0.5f};

    float acc = 0.f;
    int stride = gridDim.x * blockDim.x;
    for (int idx = blockIdx.x * blockDim.x + threadIdx.x; idx < N; idx += stride) {
        float p0 = pred[5 * idx + 0], p1 = pred[5 * idx + 1];
        float p2 = pred[5 * idx + 2], p3 = pred[5 * idx + 3], p4 = pred[5 * idx + 4];
        float t0 = target[5 * idx + 0], t1 = target[5 * idx + 1];
        float t2 = target[5 * idx + 2], t3 = target[5 * idx + 3], t4 = target[5 * idx + 4];

        // target frame: target is axis-aligned rect [-a,a]x[-b,b]
        float st, ct, sd, cd;
        __sincosf(t4, &st, &ct);
        __sincosf(p4 - t4, &sd, &cd);
        float rx = p0 - t0, ry = p1 - t1;
        float dx = ct * rx + st * ry;
        float dy = -st * rx + ct * ry;
        float a = 0.5f * t2;
        float b = 0.5f * t3;

        // pred corners in target frame (CCW)
        float qx[4], qy[4];
#pragma unroll
        for (int k = 0; k < 4; k++) {
            float cx = dxc[k] * p2, cy = dyc[k] * p3;
            qx[k] = cx * cd - cy * sd + dx;
            qy[k] = cx * sd + cy * cd + dy;
        }

        // pass 1: clamp x to [-a,a] -> 12 points (static slots)
        float px[12], py[12];
#pragma unroll
        for (int e = 0; e < 4; e++) {
            int e1 = (e + 1) & 3;
            clip_edge(qx[e], qy[e], qx[e1], qy[e1], a,
                      px[3 * e], py[3 * e],
                      px[3 * e + 1], py[3 * e + 1],
                      px[3 * e + 2], py[3 * e + 2]);
        }

        // pass 2: clamp y to [-b,b], streaming shoelace over 36 emissions
        float shl = 0.f, fx0 = 0.f, fy0 = 0.f, pvx = 0.f, pvy = 0.f;
#pragma unroll
        for (int e = 0; e < 12; e++) {
            int e1 = (e + 1 == 12) ? 0 : e + 1;
            float b0y, b0x, b1y, b1x, b2y, b2x;
            clip_edge(py[e], px[e], py[e1], px[e1], b,
                      b0y, b0x, b1y, b1x, b2y, b2x);
            if (e == 0) {
                fx0 = b0x; fy0 = b0y;  // first emitted point
                pvx = b0x; pvy = b0y;
            } else {
                shl += pvx * b0y - pvy * b0x;
                pvx = b0x; pvy = b0y;
            }
            shl += pvx * b1y - pvy * b1x;
            pvx = b1x; pvy = b1y;
            shl += pvx * b2y - pvy * b2x;
            pvx = b2x; pvy = b2y;
        }
        shl += pvx * fy0 - pvy * fx0;  // close polygon
        float overlap = fabsf(shl) * 0.5f;

        // ---- enclose: star polygon of all 8 corners (angular sort about centroid) ----
        float ex[8], ey[8];
#pragma unroll
        for (int k = 0; k < 4; k++) {
            ex[k] = qx[k];
            ey[k] = qy[k];
            ex[4 + k] = dxc[k] * t2;
            ey[4 + k] = dyc[k] * t3;
        }
        float emx = 0.f, emy = 0.f;
#pragma unroll
        for (int i = 0; i < 8; i++) { emx += ex[i]; emy += ey[i]; }
        emx *= 0.125f; emy *= 0.125f;

        unsigned kk[8];
        float kx[8], ky[8];
#pragma unroll
        for (int i = 0; i < 8; i++) {
            kk[i] = angle_key(ex[i] - emx, ey[i] - emy, i);
            kx[i] = ex[i];
            ky[i] = ey[i];
        }
        // bitonic sort of (key, x, y) triples, fully register-resident
#pragma unroll
        for (int k = 2; k <= 8; k <<= 1)
#pragma unroll
            for (int j = k >> 1; j > 0; j >>= 1)
#pragma unroll
                for (int i = 0; i < 8; i++) {
                    int l = i ^ j;
                    if (l > i) {
                        bool up = (i & k) == 0;
                        bool sw = (kk[i] > kk[l]) == up;  // need swap if out of order
                        unsigned ka = kk[i], kb = kk[l];
                        float xa = kx[i], xb = kx[l];
                        float ya = ky[i], yb = ky[l];
                        kk[i] = sw ? kb : ka; kk[l] = sw ? ka : kb;
                        kx[i] = sw ? xb : xa; kx[l] = sw ? xa : xb;
                        ky[i] = sw ? yb : ya; ky[l] = sw ? ya : yb;
                    }
                }
        float es = 0.f;
#pragma unroll
        for (int i = 0; i < 8; i++) {
            int j = (i + 1) & 7;
            es += kx[i] * ky[j] - ky[i] * kx[j];
        }
        float enclose = fabsf(es) * 0.5f;

        float uni = p2 * p3 + t2 * t3 - overlap + 1e-6f;
        float iou = fmaxf(__fdividef(overlap, uni), 1e-6f);
        float giou = iou - __fdividef(enclose - uni, enclose);
        acc += (1.f - giou) * weight[idx];
    }

    // deterministic block reduction
    float v = acc;
#pragma unroll
    for (int o = 16; o > 0; o >>= 1) v += __shfl_down_sync(0xFFFFFFFFu, v, o);
    __shared__ float ws[8];
    __shared__ bool is_last;
    int lane = threadIdx.x & 31;
    int wid = threadIdx.x >> 5;
    if (lane == 0) ws[wid] = v;
    __syncthreads();
    if (wid == 0) {
        float t = (lane < 8) ? ws[lane] : 0.f;
#pragma unroll
        for (int o = 4; o > 0; o >>= 1) t += __shfl_down_sync(0xFFFFFFFFu, t, o);
        if (lane == 0) {
            g_partial[blockIdx.x] = t;
            __threadfence();
            unsigned old = atomicAdd(&g_count, 1u);
            is_last = (old == (unsigned)(nblocks - 1));
        }
    }
    __syncthreads();

    if (is_last) {
        __threadfence();
        double s = 0.0;
        for (int i = threadIdx.x; i < nblocks; i += blockDim.x) s += (double)g_partial[i];
        __shared__ double sh[256];
        sh[threadIdx.x] = s;
        __syncthreads();
#pragma unroll
        for (int o = 128; o > 0; o >>= 1) {
            if (threadIdx.x < o) sh[threadIdx.x] += sh[threadIdx.x + o];
            __syncthreads();
        }
        if (threadIdx.x == 0) {
            out[0] = (float)(sh[0] / (double)N);
            g_count = 0u;  // reset for next graph replay
        }
    }
}

extern "C" void kernel_launch(void* const* d_in, const int* in_sizes, int n_in,
                              void* d_out, int out_size) {
    const float* pred = (const float*)d_in[0];
    const float* target = (const float*)d_in[1];
    const float* weight = (const float*)d_in[2];
    int N = in_sizes[2];

    int threads = 256;
    int blocks = (N + threads - 1) / threads;
    if (blocks > NBMAX) blocks = NBMAX;

    poly_giou_kernel<<<blocks, threads>>>(pred, target, weight, (float*)d_out, N, blocks);
}

// round 6
// speedup vs baseline: 3.0681x; 2.1081x over previous
#include <cuda_runtime.h>
#include <cstdint>

#define NBMAX 2048
__device__ float g_partial[NBMAX];
__device__ unsigned g_count;

// diamond pseudo-angle in [-2,2], monotone in atan2(cy,cx)
__device__ __forceinline__ float pseudo_angle(float cx, float cy) {
    float den = fabsf(cx) + fabsf(cy);
    den = (den == 0.f) ? 1.f : den;
    return copysignf(1.f - __fdividef(cx, den), cy);
}

// Liang-Barsky clip of segment u + t*dd, t in [0,1], against |x|<=a, |y|<=b.
// ix,iy = 1/ddx, 1/ddy. Returns clamped interval length max(t1-t0, 0).
__device__ __forceinline__ float lb_span(float ux, float uy, float ix, float iy,
                                         float a, float b) {
    float lox = (-a - ux) * ix, hix = (a - ux) * ix;
    float loy = (-b - uy) * iy, hiy = (b - uy) * iy;
    float e0 = fminf(lox, hix), e1 = fmaxf(lox, hix);
    float f0 = fminf(loy, hiy), f1 = fmaxf(loy, hiy);
    float t0 = fmaxf(fmaxf(e0, f0), 0.f);
    float t1 = fminf(fminf(e1, f1), 1.f);
    return fmaxf(t1 - t0, 0.f);
}

__global__ void __launch_bounds__(256) poly_giou_kernel(const float* __restrict__ pred,
                                                        const float* __restrict__ target,
                                                        const float* __restrict__ weight,
                                                        float* __restrict__ out,
                                                        int N, int nblocks) {
    const float dxc[4] = {0.5f, -0.5f, -0.5f, 0.5f};
    const float dyc[4] = {0.5f, 0.5f, -0.5f, -0.5f};

    float acc = 0.f;
    int stride = gridDim.x * blockDim.x;
    for (int idx = blockIdx.x * blockDim.x + threadIdx.x; idx < N; idx += stride) {
        float p0 = pred[5 * idx + 0], p1 = pred[5 * idx + 1];
        float p2 = pred[5 * idx + 2], p3 = pred[5 * idx + 3], p4 = pred[5 * idx + 4];
        float t0_ = target[5 * idx + 0], t1_ = target[5 * idx + 1];
        float t2 = target[5 * idx + 2], t3 = target[5 * idx + 3], t4 = target[5 * idx + 4];

        // target frame: target = axis rect [-a,a]x[-b,b]; pred center at d, rotated by dd=p4-t4
        float st, ct, sd, cd;
        __sincosf(t4, &st, &ct);
        __sincosf(p4 - t4, &sd, &cd);
        float rx = p0 - t0_, ry = p1 - t1_;
        float dx = ct * rx + st * ry;
        float dy = -st * rx + ct * ry;
        float a = 0.5f * t2, b = 0.5f * t3;   // target half-extents
        float a2 = 0.5f * p2, b2 = 0.5f * p3; // pred half-extents

        // pred corners in target frame (CCW)
        float qx[4], qy[4];
#pragma unroll
        for (int k = 0; k < 4; k++) {
            float cx = dxc[k] * p2, cy = dyc[k] * p3;
            qx[k] = cx * cd - cy * sd + dx;
            qy[k] = cx * sd + cy * cd + dy;
        }

        float twoI = 0.f;  // 2 * intersection area

        // ---- pred edges clipped by target rect (target frame) ----
        {
            // edge dirs: d0 = (-p2*cd, -p2*sd), d1 = (p3*sd, -p3*cd), d2=-d0, d3=-d1
            float d0x = -p2 * cd, d0y = -p2 * sd;
            float d1x = p3 * sd, d1y = -p3 * cd;
            float i0x = __fdividef(1.f, d0x), i0y = __fdividef(1.f, d0y);
            float i1x = __fdividef(1.f, d1x), i1y = __fdividef(1.f, d1y);
            float s0 = lb_span(qx[0], qy[0], i0x, i0y, a, b);
            float s1 = lb_span(qx[1], qy[1], i1x, i1y, a, b);
            float s2 = lb_span(qx[2], qy[2], -i0x, -i0y, a, b);
            float s3 = lb_span(qx[3], qy[3], -i1x, -i1y, a, b);
            twoI += s0 * (qx[0] * d0y - qy[0] * d0x);
            twoI += s1 * (qx[1] * d1y - qy[1] * d1x);
            twoI += s2 * (qx[2] * (-d0y) - qy[2] * (-d0x));
            twoI += s3 * (qx[3] * (-d1y) - qy[3] * (-d1x));
        }

        // ---- target edges clipped by pred rect (pred frame) + frame correction ----
        {
            // pred frame: map X_t -> x_p = R(-dd) X_t + d', d' = -R(-dd) d
            float dpx = -(cd * dx + sd * dy);
            float dpy = sd * dx - cd * dy;
            // target corners in pred frame (CCW)
            float ux[4], uy[4];
#pragma unroll
            for (int k = 0; k < 4; k++) {
                float cx = dxc[k] * t2, cy = dyc[k] * t3;
                ux[k] = cd * cx + sd * cy + dpx;
                uy[k] = -sd * cx + cd * cy + dpy;
            }
            // edge dirs: e0 = R(-dd)(-t2,0) = (-t2*cd, t2*sd), e1 = R(-dd)(0,-t3) = (-t3*sd, -t3*cd)
            float e0x = -t2 * cd, e0y = t2 * sd;
            float e1x = -t3 * sd, e1y = -t3 * cd;
            float j0x = __fdividef(1.f, e0x), j0y = __fdividef(1.f, e0y);
            float j1x = __fdividef(1.f, e1x), j1y = __fdividef(1.f, e1y);
            float s0 = lb_span(ux[0], uy[0], j0x, j0y, a2, b2);
            float s1 = lb_span(ux[1], uy[1], j1x, j1y, a2, b2);
            float s2 = lb_span(ux[2], uy[2], -j0x, -j0y, a2, b2);
            float s3 = lb_span(ux[3], uy[3], -j1x, -j1y, a2, b2);
            twoI += s0 * (ux[0] * e0y - uy[0] * e0x);
            twoI += s1 * (ux[1] * e1y - uy[1] * e1x);
            twoI += s2 * (ux[2] * (-e0y) - uy[2] * (-e0x));
            twoI += s3 * (ux[3] * (-e1y) - uy[3] * (-e1x));
            // translation correction: cross(d, R(dd) * sum(delta)), sum(delta) in pred frame
            float sdx = (s0 - s2) * e0x + (s1 - s3) * e1x;
            float sdy = (s0 - s2) * e0y + (s1 - s3) * e1y;
            float rsx = cd * sdx - sd * sdy;
            float rsy = sd * sdx + cd * sdy;
            twoI += dx * rsy - dy * rsx;
        }

        float overlap = fabsf(twoI) * 0.5f;

        // ---- enclose: star polygon of 8 corners, angular sort about centroid ----
        float ex[8], ey[8];
#pragma unroll
        for (int k = 0; k < 4; k++) {
            ex[k] = qx[k];
            ey[k] = qy[k];
            ex[4 + k] = dxc[k] * t2;
            ey[4 + k] = dyc[k] * t3;
        }
        float emx = 0.f, emy = 0.f;
#pragma unroll
        for (int i = 0; i < 8; i++) { emx += ex[i]; emy += ey[i]; }
        emx *= 0.125f; emy *= 0.125f;

        float ka[8], kx[8], ky[8];
#pragma unroll
        for (int i = 0; i < 8; i++) {
            ka[i] = pseudo_angle(ex[i] - emx, ey[i] - emy);
            kx[i] = ex[i];
            ky[i] = ey[i];
        }
#pragma unroll
        for (int k = 2; k <= 8; k <<= 1)
#pragma unroll
            for (int j = k >> 1; j > 0; j >>= 1)
#pragma unroll
                for (int i = 0; i < 8; i++) {
                    int l = i ^ j;
                    if (l > i) {
                        bool up = (i & k) == 0;
                        bool sw = (ka[i] > ka[l]) == up;
                        float t;
                        t = ka[i]; ka[i] = sw ? ka[l] : ka[i]; ka[l] = sw ? t : ka[l];
                        t = kx[i]; kx[i] = sw ? kx[l] : kx[i]; kx[l] = sw ? t : kx[l];
                        t = ky[i]; ky[i] = sw ? ky[l] : ky[i]; ky[l] = sw ? t : ky[l];
                    }
                }
        float es = 0.f;
#pragma unroll
        for (int i = 0; i < 8; i++) {
            int j = (i + 1) & 7;
            es += kx[i] * ky[j] - ky[i] * kx[j];
        }
        float enclose = fabsf(es) * 0.5f;

        float uni = p2 * p3 + t2 * t3 - overlap + 1e-6f;
        float iou = fmaxf(__fdividef(overlap, uni), 1e-6f);
        float giou = iou - __fdividef(enclose - uni, enclose);
        acc += (1.f - giou) * weight[idx];
    }

    // deterministic block reduction
    float v = acc;
#pragma unroll
    for (int o = 16; o > 0; o >>= 1) v += __shfl_down_sync(0xFFFFFFFFu, v, o);
    __shared__ float ws[8];
    __shared__ bool is_last;
    int lane = threadIdx.x & 31;
    int wid = threadIdx.x >> 5;
    if (lane == 0) ws[wid] = v;
    __syncthreads();
    if (wid == 0) {
        float t = (lane < 8) ? ws[lane] : 0.f;
#pragma unroll
        for (int o = 4; o > 0; o >>= 1) t += __shfl_down_sync(0xFFFFFFFFu, t, o);
        if (lane == 0) {
            g_partial[blockIdx.x] = t;
            __threadfence();
            unsigned old = atomicAdd(&g_count, 1u);
            is_last = (old == (unsigned)(nblocks - 1));
        }
    }
    __syncthreads();

    if (is_last) {
        __threadfence();
        double s = 0.0;
        for (int i = threadIdx.x; i < nblocks; i += blockDim.x) s += (double)g_partial[i];
        __shared__ double sh[256];
        sh[threadIdx.x] = s;
        __syncthreads();
#pragma unroll
        for (int o = 128; o > 0; o >>= 1) {
            if (threadIdx.x < o) sh[threadIdx.x] += sh[threadIdx.x + o];
            __syncthreads();
        }
        if (threadIdx.x == 0) {
            out[0] = (float)(sh[0] / (double)N);
            g_count = 0u;  // reset for next graph replay
        }
    }
}

extern "C" void kernel_launch(void* const* d_in, const int* in_sizes, int n_in,
                              void* d_out, int out_size) {
    const float* pred = (const float*)d_in[0];
    const float* target = (const float*)d_in[1];
    const float* weight = (const float*)d_in[2];
    int N = in_sizes[2];

    int threads = 256;
    int blocks = (N + threads - 1) / threads;
    if (blocks > NBMAX) blocks = NBMAX;

    poly_giou_kernel<<<blocks, threads>>>(pred, target, weight, (float*)d_out, N, blocks);
}

// round 7
// speedup vs baseline: 3.2259x; 1.0514x over previous
#include <cuda_runtime.h>
#include <cstdint>

#define NBMAX 2048
__device__ float g_partial[NBMAX];
__device__ unsigned g_count;

// diamond pseudo-angle in [-2,2], monotone in atan2(cy,cx)
__device__ __forceinline__ float pseudo_angle(float cx, float cy) {
    float den = fabsf(cx) + fabsf(cy);
    den = (den == 0.f) ? 1.f : den;
    return copysignf(1.f - __fdividef(cx, den), cy);
}

// Liang-Barsky clip of segment u + t*dd, t in [0,1], against |x|<=a, |y|<=b.
// ix,iy = 1/ddx, 1/ddy. Returns clamped interval length max(t1-t0, 0).
__device__ __forceinline__ float lb_span(float ux, float uy, float ix, float iy,
                                         float a, float b) {
    float lox = (-a - ux) * ix, hix = (a - ux) * ix;
    float loy = (-b - uy) * iy, hiy = (b - uy) * iy;
    float e0 = fminf(lox, hix), e1 = fmaxf(lox, hix);
    float f0 = fminf(loy, hiy), f1 = fmaxf(loy, hiy);
    float t0 = fmaxf(fmaxf(e0, f0), 0.f);
    float t1 = fminf(fminf(e1, f1), 1.f);
    return fmaxf(t1 - t0, 0.f);
}

__global__ void __launch_bounds__(256) poly_giou_kernel(const float* __restrict__ pred,
                                                        const float* __restrict__ target,
                                                        const float* __restrict__ weight,
                                                        float* __restrict__ out,
                                                        int N, int nblocks) {
    const float dxc[4] = {0.5f, -0.5f, -0.5f, 0.5f};
    const float dyc[4] = {0.5f, 0.5f, -0.5f, -0.5f};

    float acc = 0.f;
    int stride = gridDim.x * blockDim.x;
    for (int idx = blockIdx.x * blockDim.x + threadIdx.x; idx < N; idx += stride) {
        float p0 = pred[5 * idx + 0], p1 = pred[5 * idx + 1];
        float p2 = pred[5 * idx + 2], p3 = pred[5 * idx + 3], p4 = pred[5 * idx + 4];
        float t0_ = target[5 * idx + 0], t1_ = target[5 * idx + 1];
        float t2 = target[5 * idx + 2], t3 = target[5 * idx + 3], t4 = target[5 * idx + 4];

        // target frame: target = axis rect [-a,a]x[-b,b]; pred center at d, rotated by dd=p4-t4
        float st, ct, sd, cd;
        __sincosf(t4, &st, &ct);
        __sincosf(p4 - t4, &sd, &cd);
        float rx = p0 - t0_, ry = p1 - t1_;
        float dx = ct * rx + st * ry;
        float dy = -st * rx + ct * ry;
        float a = 0.5f * t2, b = 0.5f * t3;   // target half-extents
        float a2 = 0.5f * p2, b2 = 0.5f * p3; // pred half-extents

        // pred corners in target frame (CCW)
        float qx[4], qy[4];
#pragma unroll
        for (int k = 0; k < 4; k++) {
            float cx = dxc[k] * p2, cy = dyc[k] * p3;
            qx[k] = cx * cd - cy * sd + dx;
            qy[k] = cx * sd + cy * cd + dy;
        }

        float twoI = 0.f;  // 2 * intersection area

        // ---- pred edges clipped by target rect (target frame) ----
        {
            float d0x = -p2 * cd, d0y = -p2 * sd;
            float d1x = p3 * sd, d1y = -p3 * cd;
            float i0x = __fdividef(1.f, d0x), i0y = __fdividef(1.f, d0y);
            float i1x = __fdividef(1.f, d1x), i1y = __fdividef(1.f, d1y);
            float s0 = lb_span(qx[0], qy[0], i0x, i0y, a, b);
            float s1 = lb_span(qx[1], qy[1], i1x, i1y, a, b);
            float s2 = lb_span(qx[2], qy[2], -i0x, -i0y, a, b);
            float s3 = lb_span(qx[3], qy[3], -i1x, -i1y, a, b);
            twoI += s0 * (qx[0] * d0y - qy[0] * d0x);
            twoI += s1 * (qx[1] * d1y - qy[1] * d1x);
            twoI += s2 * (qx[2] * (-d0y) - qy[2] * (-d0x));
            twoI += s3 * (qx[3] * (-d1y) - qy[3] * (-d1x));
        }

        // ---- target edges clipped by pred rect (pred frame) + frame correction ----
        {
            float dpx = -(cd * dx + sd * dy);
            float dpy = sd * dx - cd * dy;
            float ux[4], uy[4];
#pragma unroll
            for (int k = 0; k < 4; k++) {
                float cx = dxc[k] * t2, cy = dyc[k] * t3;
                ux[k] = cd * cx + sd * cy + dpx;
                uy[k] = -sd * cx + cd * cy + dpy;
            }
            float e0x = -t2 * cd, e0y = t2 * sd;
            float e1x = -t3 * sd, e1y = -t3 * cd;
            float j0x = __fdividef(1.f, e0x), j0y = __fdividef(1.f, e0y);
            float j1x = __fdividef(1.f, e1x), j1y = __fdividef(1.f, e1y);
            float s0 = lb_span(ux[0], uy[0], j0x, j0y, a2, b2);
            float s1 = lb_span(ux[1], uy[1], j1x, j1y, a2, b2);
            float s2 = lb_span(ux[2], uy[2], -j0x, -j0y, a2, b2);
            float s3 = lb_span(ux[3], uy[3], -j1x, -j1y, a2, b2);
            twoI += s0 * (ux[0] * e0y - uy[0] * e0x);
            twoI += s1 * (ux[1] * e1y - uy[1] * e1x);
            twoI += s2 * (ux[2] * (-e0y) - uy[2] * (-e0x));
            twoI += s3 * (ux[3] * (-e1y) - uy[3] * (-e1x));
            float sdx = (s0 - s2) * e0x + (s1 - s3) * e1x;
            float sdy = (s0 - s2) * e0y + (s1 - s3) * e1y;
            float rsx = cd * sdx - sd * sdy;
            float rsy = sd * sdx + cd * sdy;
            twoI += dx * rsy - dy * rsx;
        }

        float overlap = fabsf(twoI) * 0.5f;

        // ---- enclose: star polygon of 8 corners about exact centroid (dx/2, dy/2) ----
        // (target corner sum = 0, pred corner offsets cancel in +/- pairs)
        float mx = 0.5f * dx, my = 0.5f * dy;
        float vx[8], vy[8], ka[8];
#pragma unroll
        for (int k = 0; k < 4; k++) {
            vx[k] = qx[k] - mx;
            vy[k] = qy[k] - my;
            vx[4 + k] = dxc[k] * t2 - mx;
            vy[4 + k] = dyc[k] * t3 - my;
        }
#pragma unroll
        for (int i = 0; i < 8; i++) ka[i] = pseudo_angle(vx[i], vy[i]);

        // Batcher odd-even merge sort, 19 ascending comparators
#define CE(I, J)                                                   \
        {                                                          \
            bool sw = ka[I] > ka[J];                               \
            float t;                                               \
            t = ka[I]; ka[I] = sw ? ka[J] : ka[I]; ka[J] = sw ? t : ka[J]; \
            t = vx[I]; vx[I] = sw ? vx[J] : vx[I]; vx[J] = sw ? t : vx[J]; \
            t = vy[I]; vy[I] = sw ? vy[J] : vy[I]; vy[J] = sw ? t : vy[J]; \
        }
        CE(0, 1) CE(2, 3) CE(4, 5) CE(6, 7)
        CE(0, 2) CE(1, 3) CE(4, 6) CE(5, 7)
        CE(1, 2) CE(5, 6)
        CE(0, 4) CE(1, 5) CE(2, 6) CE(3, 7)
        CE(2, 4) CE(3, 5)
        CE(1, 2) CE(3, 4) CE(5, 6)
#undef CE

        float es = 0.f;
#pragma unroll
        for (int i = 0; i < 8; i++) {
            int j = (i + 1) & 7;
            es += vx[i] * vy[j] - vy[i] * vx[j];  // translation-invariant shoelace
        }
        float enclose = fabsf(es) * 0.5f;

        float uni = p2 * p3 + t2 * t3 - overlap + 1e-6f;
        float iou = fmaxf(__fdividef(overlap, uni), 1e-6f);
        float giou = iou - __fdividef(enclose - uni, enclose);
        acc += (1.f - giou) * weight[idx];
    }

    // deterministic block reduction
    float v = acc;
#pragma unroll
    for (int o = 16; o > 0; o >>= 1) v += __shfl_down_sync(0xFFFFFFFFu, v, o);
    __shared__ float ws[8];
    __shared__ bool is_last;
    int lane = threadIdx.x & 31;
    int wid = threadIdx.x >> 5;
    if (lane == 0) ws[wid] = v;
    __syncthreads();
    if (wid == 0) {
        float t = (lane < 8) ? ws[lane] : 0.f;
#pragma unroll
        for (int o = 4; o > 0; o >>= 1) t += __shfl_down_sync(0xFFFFFFFFu, t, o);
        if (lane == 0) {
            g_partial[blockIdx.x] = t;
            __threadfence();
            unsigned old = atomicAdd(&g_count, 1u);
            is_last = (old == (unsigned)(nblocks - 1));
        }
    }
    __syncthreads();

    if (is_last) {
        __threadfence();
        double s = 0.0;
        for (int i = threadIdx.x; i < nblocks; i += blockDim.x) s += (double)g_partial[i];
        __shared__ double sh[256];
        sh[threadIdx.x] = s;
        __syncthreads();
#pragma unroll
        for (int o = 128; o > 0; o >>= 1) {
            if (threadIdx.x < o) sh[threadIdx.x] += sh[threadIdx.x + o];
            __syncthreads();
        }
        if (threadIdx.x == 0) {
            out[0] = (float)(sh[0] / (double)N);
            g_count = 0u;  // reset for next graph replay
        }
    }
}

extern "C" void kernel_launch(void* const* d_in, const int* in_sizes, int n_in,
                              void* d_out, int out_size) {
    const float* pred = (const float*)d_in[0];
    const float* target = (const float*)d_in[1];
    const float* weight = (const float*)d_in[2];
    int N = in_sizes[2];

    int threads = 256;
    int blocks = (N + threads - 1) / threads;
    if (blocks > NBMAX) blocks = NBMAX;

    poly_giou_kernel<<<blocks, threads>>>(pred, target, weight, (float*)d_out, N, blocks);
}